// round 13
// baseline (speedup 1.0000x reference)
#include <cuda_runtime.h>
#include <math.h>

#define T_SEQ   8192
#define NBATCH  2
#define NROWS   (NBATCH * T_SEQ)   // 16384
#define WIN     512                // gamma^512 ~ 8.7e-8: truncation safe at 1e-3
#define L2G     (-0.04580369f)     // log2(0.96875)

// ---------------- scratch (device globals; no allocs allowed) ----------------
__device__ float g_Q[NROWS * 64];
__device__ float g_K[NROWS * 64];
__device__ float g_V[NROWS * 64];

__device__ __forceinline__ float to_tf32(float x) {
    unsigned u; asm("cvt.rna.tf32.f32 %0, %1;" : "=r"(u) : "f"(x));
    return __uint_as_float(u);
}

// m16n8k8 tf32 warp MMA (family-agnostic PTX, compiles for compute_103)
__device__ __forceinline__ void mma_tf32(float& d0, float& d1, float& d2, float& d3,
                                         unsigned a0, unsigned a1, unsigned a2, unsigned a3,
                                         unsigned b0, unsigned b1) {
    asm volatile("mma.sync.aligned.m16n8k8.row.col.f32.tf32.tf32.f32 "
                 "{%0,%1,%2,%3}, {%4,%5,%6,%7}, {%8,%9}, {%0,%1,%2,%3};"
                 : "+f"(d0), "+f"(d1), "+f"(d2), "+f"(d3)
                 : "r"(a0), "r"(a1), "r"(a2), "r"(a3), "r"(b0), "r"(b1));
}

// =================== Kernel 1: QKV proj (3xTF32 tensor-core) =================
#define LDXP 68    // X smem pad: frag banks gi*4+ti4 -> conflict-free
#define LDW  200   // W smem pad: 200 mod 32 = 8 -> frag banks ti4*8+gi -> CF
#define PROJ_SMEM ((64 * LDXP + 64 * LDW) * 4)   // 68608 B

__global__ __launch_bounds__(256, 2) void proj_kernel(
    const float* __restrict__ X,
    const float* __restrict__ WQ,
    const float* __restrict__ WK,
    const float* __restrict__ WV)
{
    extern __shared__ float sm[];
    float* Xs = sm;                // [64][LDXP]
    float* Ws = sm + 64 * LDXP;    // [64 k][LDW], cols 0..191 = WQ|WK|WV

    const int tid  = threadIdx.x;
    const int lane = tid & 31;
    const int w    = tid >> 5;
    const int gi   = lane >> 2;
    const int ti4  = lane & 3;
    const int wr   = w & 3;        // row group
    const int wh   = w >> 2;       // column half
    const int r0   = blockIdx.x * 64;

    for (int idx = tid; idx < 64 * 16; idx += 256) {
        int row = idx >> 4, c4 = (idx & 15) << 2;
        *(float4*)&Xs[row * LDXP + c4] = *(const float4*)&X[(r0 + row) * 64 + c4];
    }
    {
        const float* Wsrc[3] = {WQ, WK, WV};
        #pragma unroll
        for (int m = 0; m < 3; m++)
            for (int idx = tid; idx < 64 * 16; idx += 256) {
                int row = idx >> 4, c4 = (idx & 15) << 2;
                *(float4*)&Ws[row * LDW + m * 64 + c4] =
                    *(const float4*)&Wsrc[m][row * 64 + c4];
            }
    }
    __syncthreads();

    const int qrow = wr * 16 + gi;
    unsigned ahi[8][4], alo[8][4];
    #pragma unroll
    for (int k0 = 0; k0 < 8; k0++) {
        float xv[4];
        xv[0] = Xs[qrow * LDXP + k0 * 8 + ti4];
        xv[1] = Xs[(qrow + 8) * LDXP + k0 * 8 + ti4];
        xv[2] = Xs[qrow * LDXP + k0 * 8 + ti4 + 4];
        xv[3] = Xs[(qrow + 8) * LDXP + k0 * 8 + ti4 + 4];
        #pragma unroll
        for (int u = 0; u < 4; u++) {
            float hi = to_tf32(xv[u]);
            ahi[k0][u] = __float_as_uint(hi);
            alo[k0][u] = __float_as_uint(to_tf32(xv[u] - hi));
        }
    }

    float* outp[3] = {g_Q, g_K, g_V};
    for (int m = 0; m < 3; m++) {
        float accA[4][4], accB[4][4];
        #pragma unroll
        for (int nt = 0; nt < 4; nt++)
            #pragma unroll
            for (int u = 0; u < 4; u++) { accA[nt][u] = 0.f; accB[nt][u] = 0.f; }

        #pragma unroll
        for (int k0 = 0; k0 < 8; k0++) {
            #pragma unroll
            for (int ntl = 0; ntl < 4; ntl++) {
                const int ncol = m * 64 + (wh * 4 + ntl) * 8 + gi;
                float b0f = Ws[(k0 * 8 + ti4) * LDW + ncol];
                float b1f = Ws[(k0 * 8 + ti4 + 4) * LDW + ncol];
                float b0h = to_tf32(b0f), b1h = to_tf32(b1f);
                unsigned ub0h = __float_as_uint(b0h);
                unsigned ub1h = __float_as_uint(b1h);
                unsigned ub0l = __float_as_uint(to_tf32(b0f - b0h));
                unsigned ub1l = __float_as_uint(to_tf32(b1f - b1h));
                mma_tf32(accA[ntl][0], accA[ntl][1], accA[ntl][2], accA[ntl][3],
                         ahi[k0][0], ahi[k0][1], ahi[k0][2], ahi[k0][3], ub0h, ub1h);
                mma_tf32(accB[ntl][0], accB[ntl][1], accB[ntl][2], accB[ntl][3],
                         ahi[k0][0], ahi[k0][1], ahi[k0][2], ahi[k0][3], ub0l, ub1l);
                mma_tf32(accB[ntl][0], accB[ntl][1], accB[ntl][2], accB[ntl][3],
                         alo[k0][0], alo[k0][1], alo[k0][2], alo[k0][3], ub0h, ub1h);
            }
        }
        float* op = outp[m];
        #pragma unroll
        for (int ntl = 0; ntl < 4; ntl++) {
            int col = (wh * 4 + ntl) * 8 + 2 * ti4;
            *(float2*)&op[(r0 + qrow) * 64 + col] =
                make_float2(accA[ntl][0] + accB[ntl][0], accA[ntl][1] + accB[ntl][1]);
            *(float2*)&op[(r0 + qrow + 8) * 64 + col] =
                make_float2(accA[ntl][2] + accB[ntl][2], accA[ntl][3] + accB[ntl][3]);
        }
    }
}

// ========== Kernel 2: warp-MMA tf32 attention, intra-CTA window split ========
// CTA = 64 q-rows, 256 threads = 2 warp-groups x 4 warps. wg0 takes first half
// of the key-tile list, wg1 the second half (incl. diagonal). Private K/V smem
// per wg, named-barrier sync. Final: wg1 partial O -> smem, wg0 adds + fused GN
// + transposed store.
#define LDP 68   // pad for Q/K/S
#define LDV 72   // pad for V

#define SM_BINV 0
#define SM_QS   64                       // [64][LDP]; wg0 S alias + combine buf
#define SM_KS0  (SM_QS  + 64 * LDP)
#define SM_VS0  (SM_KS0 + 64 * LDP)
#define SM_KS1  (SM_VS0 + 64 * LDV)
#define SM_VS1  (SM_KS1 + 64 * LDP)
#define SM_SS1  (SM_VS1 + 64 * LDV)      // [64][LDP] wg1 S buffer
#define ATTN_SMEM ((SM_SS1 + 64 * LDP) * 4)   // 106752 B

__global__ __launch_bounds__(256, 1) void attn_kernel(
    const float* __restrict__ gw, const float* __restrict__ gb,
    float* __restrict__ out)
{
    extern __shared__ float sm[];
    float* binv = sm + SM_BINV;
    float* Qs   = sm + SM_QS;

    const int tid  = threadIdx.x;
    const int lane = tid & 31;
    const int w    = tid >> 5;
    const int wg   = w >> 2;      // warp group 0/1
    const int wl   = w & 3;       // warp within group
    const int wtid = tid & 127;   // thread within group
    const int gi   = lane >> 2;   // 0..7
    const int ti4  = lane & 3;    // 0..3

    float* Ks = sm + (wg ? SM_KS1 : SM_KS0);
    float* Vs = sm + (wg ? SM_VS1 : SM_VS0);

    const int r0 = blockIdx.x * 64;
    const int b  = r0 >> 13;
    const int t0 = r0 & (T_SEQ - 1);
    const int bT = b << 13;

    if (tid < 64) binv[tid] = exp2f(-(float)tid * L2G);   // gamma^-j

    // ---- stage Q (tf32), CTA-wide ----
    for (int idx = tid; idx < 64 * 16; idx += 256) {
        int row = idx >> 4, c4 = (idx & 15) << 2;
        float4 v = *(const float4*)&g_Q[(r0 + row) * 64 + c4];
        v.x = to_tf32(v.x); v.y = to_tf32(v.y); v.z = to_tf32(v.z); v.w = to_tf32(v.w);
        *(float4*)&Qs[row * LDP + c4] = v;
    }
    __syncthreads();

    // ---- Q fragments (same rows for both wgs) ----
    const int qr = wl * 16;
    unsigned qa[8][4];
    #pragma unroll
    for (int k0 = 0; k0 < 8; k0++) {
        int base = (qr + gi) * LDP + k0 * 8 + ti4;
        qa[k0][0] = __float_as_uint(Qs[base]);
        qa[k0][1] = __float_as_uint(Qs[base + 8 * LDP]);
        qa[k0][2] = __float_as_uint(Qs[base + 4]);
        qa[k0][3] = __float_as_uint(Qs[base + 8 * LDP + 4]);
    }
    __syncthreads();   // qa reads done before wg0 overwrites Qs with S

    float o[8][4];
    #pragma unroll
    for (int nt = 0; nt < 8; nt++)
        #pragma unroll
        for (int u = 0; u < 4; u++) o[nt][u] = 0.f;

    // wg0: S aliases Qs (dead); wg1: private SS1 region
    float* sw = (wg ? sm + SM_SS1 : Qs) + qr * LDP;

    // tile list split between warp groups
    int ks = t0 - WIN; if (ks < 0) ks = 0;
    const int nt_all = (t0 + 64 - ks) >> 6;
    const int nh     = nt_all >> 1;
    const int i_beg  = wg ? nh : 0;
    const int i_end  = wg ? nt_all : nh;
    const int barid  = 1 + wg;

    for (int it = i_beg; it < i_end; it++) {
        const int s0 = ks + (it << 6);

        // ---- stage K, V tiles (tf32), wg-private ----
        for (int idx = wtid; idx < 64 * 16; idx += 128) {
            int key = idx >> 4, c4 = (idx & 15) << 2;
            float4 kv = *(const float4*)&g_K[(bT + s0 + key) * 64 + c4];
            kv.x = to_tf32(kv.x); kv.y = to_tf32(kv.y);
            kv.z = to_tf32(kv.z); kv.w = to_tf32(kv.w);
            *(float4*)&Ks[key * LDP + c4] = kv;
            float4 vv = *(const float4*)&g_V[(bT + s0 + key) * 64 + c4];
            vv.x = to_tf32(vv.x); vv.y = to_tf32(vv.y);
            vv.z = to_tf32(vv.z); vv.w = to_tf32(vv.w);
            *(float4*)&Vs[key * LDV + c4] = vv;
        }
        asm volatile("bar.sync %0, 128;" :: "r"(barid) : "memory");

        const int   dr0 = t0 + qr + gi - s0;
        const float ai0 = exp2f((float)dr0 * L2G);
        const float ai1 = exp2f((float)(dr0 + 8) * L2G);

        // ---- stage 1: S = Q K^T (k0-outer) ----
        float s[8][4];
        #pragma unroll
        for (int nt = 0; nt < 8; nt++)
            #pragma unroll
            for (int u = 0; u < 4; u++) s[nt][u] = 0.f;

        #pragma unroll
        for (int k0 = 0; k0 < 8; k0++) {
            #pragma unroll
            for (int nt = 0; nt < 8; nt++) {
                int ba = (nt * 8 + gi) * LDP + k0 * 8 + ti4;
                unsigned b0 = __float_as_uint(Ks[ba]);
                unsigned b1 = __float_as_uint(Ks[ba + 4]);
                mma_tf32(s[nt][0], s[nt][1], s[nt][2], s[nt][3],
                         qa[k0][0], qa[k0][1], qa[k0][2], qa[k0][3], b0, b1);
            }
        }

        // ---- decay + causal mask, tf32, to S buffer ----
        #pragma unroll
        for (int nt = 0; nt < 8; nt++) {
            const int je = nt * 8 + 2 * ti4, jo = je + 1;
            const float be = binv[je], bo = binv[jo];
            float c0 = (dr0     >= je) ? s[nt][0] * ai0 * be : 0.f;
            float c1 = (dr0     >= jo) ? s[nt][1] * ai0 * bo : 0.f;
            float c2 = (dr0 + 8 >= je) ? s[nt][2] * ai1 * be : 0.f;
            float c3 = (dr0 + 8 >= jo) ? s[nt][3] * ai1 * bo : 0.f;
            *(float2*)&sw[gi * LDP + je]       = make_float2(to_tf32(c0), to_tf32(c1));
            *(float2*)&sw[(gi + 8) * LDP + je] = make_float2(to_tf32(c2), to_tf32(c3));
        }
        __syncwarp();

        // ---- A fragments of S ----
        unsigned sa[8][4];
        #pragma unroll
        for (int k0 = 0; k0 < 8; k0++) {
            int base = gi * LDP + k0 * 8 + ti4;
            sa[k0][0] = __float_as_uint(sw[base]);
            sa[k0][1] = __float_as_uint(sw[base + 8 * LDP]);
            sa[k0][2] = __float_as_uint(sw[base + 4]);
            sa[k0][3] = __float_as_uint(sw[base + 8 * LDP + 4]);
        }

        // ---- stage 2: O += S V (k0-outer) ----
        #pragma unroll
        for (int k0 = 0; k0 < 8; k0++) {
            #pragma unroll
            for (int nt = 0; nt < 8; nt++) {
                int va = (k0 * 8 + ti4) * LDV + nt * 8 + gi;
                unsigned b0 = __float_as_uint(Vs[va]);
                unsigned b1 = __float_as_uint(Vs[va + 4 * LDV]);
                mma_tf32(o[nt][0], o[nt][1], o[nt][2], o[nt][3],
                         sa[k0][0], sa[k0][1], sa[k0][2], sa[k0][3], b0, b1);
            }
        }
        asm volatile("bar.sync %0, 128;" :: "r"(barid) : "memory");
    }

    // ---- combine wg1 partials into wg0 (smem, pad-33 conflict-free) ----
    __syncthreads();                        // both wgs done; Qs free
    float* cmb = sm + SM_QS;                // 128*33 floats = 4224 <= 64*LDP
    if (wg == 1) {
        float* dst = cmb + wtid * 33;
        #pragma unroll
        for (int nt = 0; nt < 8; nt++) {
            dst[nt * 4 + 0] = o[nt][0]; dst[nt * 4 + 1] = o[nt][1];
            dst[nt * 4 + 2] = o[nt][2]; dst[nt * 4 + 3] = o[nt][3];
        }
    }
    __syncthreads();

    if (wg == 0) {
        const float* src = cmb + wtid * 33;
        #pragma unroll
        for (int nt = 0; nt < 8; nt++) {
            o[nt][0] += src[nt * 4 + 0]; o[nt][1] += src[nt * 4 + 1];
            o[nt][2] += src[nt * 4 + 2]; o[nt][3] += src[nt * 4 + 3];
        }

        // ---- fused GroupNorm + transposed store ----
        const int t_lo = t0 + qr + gi;
        float* outb = out + (size_t)b * T_SEQ * 64;

        #pragma unroll
        for (int nt = 0; nt < 8; nt++) {
            float sl = o[nt][0] + o[nt][1];
            float ql = fmaf(o[nt][0], o[nt][0], o[nt][1] * o[nt][1]);
            float sh = o[nt][2] + o[nt][3];
            float qh = fmaf(o[nt][2], o[nt][2], o[nt][3] * o[nt][3]);
            sl += __shfl_xor_sync(0xffffffffu, sl, 1);
            ql += __shfl_xor_sync(0xffffffffu, ql, 1);
            sh += __shfl_xor_sync(0xffffffffu, sh, 1);
            qh += __shfl_xor_sync(0xffffffffu, qh, 1);
            sl += __shfl_xor_sync(0xffffffffu, sl, 2);
            ql += __shfl_xor_sync(0xffffffffu, ql, 2);
            sh += __shfl_xor_sync(0xffffffffu, sh, 2);
            qh += __shfl_xor_sync(0xffffffffu, qh, 2);

            float mul = sl * 0.125f, muh = sh * 0.125f;
            float rl = rsqrtf(fmaf(-mul, mul, ql * 0.125f) + 1e-6f);
            float rh = rsqrtf(fmaf(-muh, muh, qh * 0.125f) + 1e-6f);

            const int c0 = nt * 8 + 2 * ti4, c1 = c0 + 1;
            const float w0 = gw[c0], w1 = gw[c1];
            const float b0 = gb[c0], b1 = gb[c1];
            outb[(size_t)c0 * T_SEQ + t_lo]     = (o[nt][0] - mul) * rl * w0 + b0;
            outb[(size_t)c1 * T_SEQ + t_lo]     = (o[nt][1] - mul) * rl * w1 + b1;
            outb[(size_t)c0 * T_SEQ + t_lo + 8] = (o[nt][2] - muh) * rh * w0 + b0;
            outb[(size_t)c1 * T_SEQ + t_lo + 8] = (o[nt][3] - muh) * rh * w1 + b1;
        }
    }
}

// =============================================================================
extern "C" void kernel_launch(void* const* d_in, const int* in_sizes, int n_in,
                              void* d_out, int out_size)
{
    (void)in_sizes; (void)n_in; (void)out_size;
    const float* X  = (const float*)d_in[0];
    const float* WQ = (const float*)d_in[1];
    const float* WK = (const float*)d_in[2];
    const float* WV = (const float*)d_in[3];
    const float* gw = (const float*)d_in[4];
    const float* gb = (const float*)d_in[5];
    float* out = (float*)d_out;

    cudaFuncSetAttribute(proj_kernel, cudaFuncAttributeMaxDynamicSharedMemorySize, PROJ_SMEM);
    cudaFuncSetAttribute(attn_kernel, cudaFuncAttributeMaxDynamicSharedMemorySize, ATTN_SMEM);

    proj_kernel<<<NROWS / 64, 256, PROJ_SMEM>>>(X, WQ, WK, WV);
    attn_kernel<<<NROWS / 64, 256, ATTN_SMEM>>>(gw, gb, out);
}

// round 14
// speedup vs baseline: 1.1145x; 1.1145x over previous
#include <cuda_runtime.h>
#include <math.h>

#define T_SEQ   8192
#define NBATCH  2
#define NROWS   (NBATCH * T_SEQ)   // 16384
#define WIN     448                // gamma^448/(1-gamma) ~ 2e-5: safe at 1e-3
#define L2G     (-0.04580369f)     // log2(0.96875)

// ---------------- scratch (device globals; no allocs allowed) ----------------
__device__ float g_Q[NROWS * 64];
__device__ float g_K[NROWS * 64];
__device__ float g_V[NROWS * 64];

__device__ __forceinline__ float to_tf32(float x) {
    unsigned u; asm("cvt.rna.tf32.f32 %0, %1;" : "=r"(u) : "f"(x));
    return __uint_as_float(u);
}
__device__ __forceinline__ unsigned smem_u32(const void* p) {
    unsigned a;
    asm("{ .reg .u64 t; cvta.to.shared.u64 t, %1; cvt.u32.u64 %0, t; }"
        : "=r"(a) : "l"(p));
    return a;
}
__device__ __forceinline__ void cp16(unsigned dst, const void* src) {
    asm volatile("cp.async.ca.shared.global [%0], [%1], 16;"
                 :: "r"(dst), "l"(src) : "memory");
}
#define CP_COMMIT() asm volatile("cp.async.commit_group;" ::: "memory")
#define CP_WAIT0()  asm volatile("cp.async.wait_group 0;" ::: "memory")

// m16n8k8 tf32 warp MMA (family-agnostic PTX, compiles for compute_103)
__device__ __forceinline__ void mma_tf32(float& d0, float& d1, float& d2, float& d3,
                                         unsigned a0, unsigned a1, unsigned a2, unsigned a3,
                                         unsigned b0, unsigned b1) {
    asm volatile("mma.sync.aligned.m16n8k8.row.col.f32.tf32.tf32.f32 "
                 "{%0,%1,%2,%3}, {%4,%5,%6,%7}, {%8,%9}, {%0,%1,%2,%3};"
                 : "+f"(d0), "+f"(d1), "+f"(d2), "+f"(d3)
                 : "r"(a0), "r"(a1), "r"(a2), "r"(a3), "r"(b0), "r"(b1));
}

// =================== Kernel 1: QKV proj (3xTF32 tensor-core) =================
#define LDXP 68    // X smem pad: frag banks gi*4+ti4 -> conflict-free
#define LDW  200   // W smem pad: 200 mod 32 = 8 -> frag banks ti4*8+gi -> CF
#define PROJ_SMEM ((64 * LDXP + 64 * LDW) * 4)   // 68608 B

__global__ __launch_bounds__(256, 2) void proj_kernel(
    const float* __restrict__ X,
    const float* __restrict__ WQ,
    const float* __restrict__ WK,
    const float* __restrict__ WV)
{
    extern __shared__ float sm[];
    float* Xs = sm;                // [64][LDXP]
    float* Ws = sm + 64 * LDXP;    // [64 k][LDW], cols 0..191 = WQ|WK|WV

    const int tid  = threadIdx.x;
    const int lane = tid & 31;
    const int w    = tid >> 5;
    const int gi   = lane >> 2;
    const int ti4  = lane & 3;
    const int wr   = w & 3;        // row group
    const int wh   = w >> 2;       // column half
    const int r0   = blockIdx.x * 64;

    for (int idx = tid; idx < 64 * 16; idx += 256) {
        int row = idx >> 4, c4 = (idx & 15) << 2;
        *(float4*)&Xs[row * LDXP + c4] = *(const float4*)&X[(r0 + row) * 64 + c4];
    }
    {
        const float* Wsrc[3] = {WQ, WK, WV};
        #pragma unroll
        for (int m = 0; m < 3; m++)
            for (int idx = tid; idx < 64 * 16; idx += 256) {
                int row = idx >> 4, c4 = (idx & 15) << 2;
                *(float4*)&Ws[row * LDW + m * 64 + c4] =
                    *(const float4*)&Wsrc[m][row * 64 + c4];
            }
    }
    __syncthreads();

    const int qrow = wr * 16 + gi;
    unsigned ahi[8][4], alo[8][4];
    #pragma unroll
    for (int k0 = 0; k0 < 8; k0++) {
        float xv[4];
        xv[0] = Xs[qrow * LDXP + k0 * 8 + ti4];
        xv[1] = Xs[(qrow + 8) * LDXP + k0 * 8 + ti4];
        xv[2] = Xs[qrow * LDXP + k0 * 8 + ti4 + 4];
        xv[3] = Xs[(qrow + 8) * LDXP + k0 * 8 + ti4 + 4];
        #pragma unroll
        for (int u = 0; u < 4; u++) {
            float hi = to_tf32(xv[u]);
            ahi[k0][u] = __float_as_uint(hi);
            alo[k0][u] = __float_as_uint(to_tf32(xv[u] - hi));
        }
    }

    float* outp[3] = {g_Q, g_K, g_V};
    for (int m = 0; m < 3; m++) {
        float accA[4][4], accB[4][4];
        #pragma unroll
        for (int nt = 0; nt < 4; nt++)
            #pragma unroll
            for (int u = 0; u < 4; u++) { accA[nt][u] = 0.f; accB[nt][u] = 0.f; }

        #pragma unroll
        for (int k0 = 0; k0 < 8; k0++) {
            #pragma unroll
            for (int ntl = 0; ntl < 4; ntl++) {
                const int ncol = m * 64 + (wh * 4 + ntl) * 8 + gi;
                float b0f = Ws[(k0 * 8 + ti4) * LDW + ncol];
                float b1f = Ws[(k0 * 8 + ti4 + 4) * LDW + ncol];
                float b0h = to_tf32(b0f), b1h = to_tf32(b1f);
                unsigned ub0h = __float_as_uint(b0h);
                unsigned ub1h = __float_as_uint(b1h);
                unsigned ub0l = __float_as_uint(to_tf32(b0f - b0h));
                unsigned ub1l = __float_as_uint(to_tf32(b1f - b1h));
                mma_tf32(accA[ntl][0], accA[ntl][1], accA[ntl][2], accA[ntl][3],
                         ahi[k0][0], ahi[k0][1], ahi[k0][2], ahi[k0][3], ub0h, ub1h);
                mma_tf32(accB[ntl][0], accB[ntl][1], accB[ntl][2], accB[ntl][3],
                         ahi[k0][0], ahi[k0][1], ahi[k0][2], ahi[k0][3], ub0l, ub1l);
                mma_tf32(accB[ntl][0], accB[ntl][1], accB[ntl][2], accB[ntl][3],
                         alo[k0][0], alo[k0][1], alo[k0][2], alo[k0][3], ub0h, ub1h);
            }
        }
        float* op = outp[m];
        #pragma unroll
        for (int ntl = 0; ntl < 4; ntl++) {
            int col = (wh * 4 + ntl) * 8 + 2 * ti4;
            *(float2*)&op[(r0 + qrow) * 64 + col] =
                make_float2(accA[ntl][0] + accB[ntl][0], accA[ntl][1] + accB[ntl][1]);
            *(float2*)&op[(r0 + qrow + 8) * 64 + col] =
                make_float2(accA[ntl][2] + accB[ntl][2], accA[ntl][3] + accB[ntl][3]);
        }
    }
}

// ======= Kernel 2: warp-MMA tf32 attention + fused GN, cp.async pipeline =====
// CTA = 64 q-rows, 4 warps x 16 rows, 128 threads, grid 256. Key tiles of 64.
// Double-buffered K/V via cp.async; in-smem tf32 rounding pass after arrival
// (numerics identical to pre-rounded staging). S aliases Qs. GN fused epilogue.
#define LDP 68   // pad for Q/K/S
#define LDV 72   // pad for V

#define SM_BINV 0
#define SM_QS   64                          // [64][LDP]; reused as S buffer
#define SM_KV   (SM_QS + 64 * LDP)          // 2 x { K:[64][LDP], V:[64][LDV] }
#define KVBUF   (64 * LDP + 64 * LDV)
#define ATTN_SMEM ((SM_KV + 2 * KVBUF) * 4) // 89344 B

__global__ __launch_bounds__(128, 2) void attn_kernel(
    const float* __restrict__ gw, const float* __restrict__ gb,
    float* __restrict__ out)
{
    extern __shared__ float sm[];
    float* binv = sm + SM_BINV;
    float* Qs   = sm + SM_QS;
    const unsigned sbase = smem_u32(sm);

    const int tid  = threadIdx.x;
    const int lane = tid & 31;
    const int w    = tid >> 5;
    const int gi   = lane >> 2;   // 0..7
    const int ti4  = lane & 3;    // 0..3

    const int r0 = blockIdx.x * 64;
    const int b  = r0 >> 13;
    const int t0 = r0 & (T_SEQ - 1);
    const int bT = b << 13;

    if (tid < 64) binv[tid] = exp2f(-(float)tid * L2G);   // gamma^-j

    // ---- stage Q (tf32) ----
    for (int idx = tid; idx < 64 * 16; idx += 128) {
        int row = idx >> 4, c4 = (idx & 15) << 2;
        float4 v = *(const float4*)&g_Q[(r0 + row) * 64 + c4];
        v.x = to_tf32(v.x); v.y = to_tf32(v.y); v.z = to_tf32(v.z); v.w = to_tf32(v.w);
        *(float4*)&Qs[row * LDP + c4] = v;
    }
    __syncthreads();

    // ---- Q fragments, register-resident for all tiles ----
    const int qr = w * 16;
    unsigned qa[8][4];
    #pragma unroll
    for (int k0 = 0; k0 < 8; k0++) {
        int base = (qr + gi) * LDP + k0 * 8 + ti4;
        qa[k0][0] = __float_as_uint(Qs[base]);
        qa[k0][1] = __float_as_uint(Qs[base + 8 * LDP]);
        qa[k0][2] = __float_as_uint(Qs[base + 4]);
        qa[k0][3] = __float_as_uint(Qs[base + 8 * LDP + 4]);
    }

    float o[8][4];
    #pragma unroll
    for (int nt = 0; nt < 8; nt++)
        #pragma unroll
        for (int u = 0; u < 4; u++) o[nt][u] = 0.f;

    float* sw = Qs + qr * LDP;      // warp-private S buffer (aliases this warp's Q rows)

    int ks = t0 - WIN; if (ks < 0) ks = 0;
    const int ntile = (t0 + 64 - ks) >> 6;

    // ---- prologue: async-stage tile 0 into buffer 0 ----
    {
        const int s0 = ks;
        #pragma unroll 2
        for (int idx = tid; idx < 64 * 16; idx += 128) {
            int key = idx >> 4, c4 = (idx & 15) << 2;
            cp16(sbase + (SM_KV + key * LDP + c4) * 4,
                 &g_K[(bT + s0 + key) * 64 + c4]);
            cp16(sbase + (SM_KV + 64 * LDP + key * LDV + c4) * 4,
                 &g_V[(bT + s0 + key) * 64 + c4]);
        }
        CP_COMMIT();
    }

    for (int it = 0; it < ntile; it++) {
        const int s0  = ks + (it << 6);
        const int buf = it & 1;
        float* Ks = sm + SM_KV + buf * KVBUF;
        float* Vs = Ks + 64 * LDP;

        CP_WAIT0();
        __syncthreads();          // tile it arrived everywhere; buf^1 compute done

        // ---- prefetch tile it+1 into the other buffer ----
        if (it + 1 < ntile) {
            const int s1 = s0 + 64;
            const int obase = SM_KV + (buf ^ 1) * KVBUF;
            #pragma unroll 2
            for (int idx = tid; idx < 64 * 16; idx += 128) {
                int key = idx >> 4, c4 = (idx & 15) << 2;
                cp16(sbase + (obase + key * LDP + c4) * 4,
                     &g_K[(bT + s1 + key) * 64 + c4]);
                cp16(sbase + (obase + 64 * LDP + key * LDV + c4) * 4,
                     &g_V[(bT + s1 + key) * 64 + c4]);
            }
            CP_COMMIT();
        }

        // ---- in-place tf32 rounding pass (keeps numerics = pre-rounded) ----
        #pragma unroll 2
        for (int idx = tid; idx < 64 * 16; idx += 128) {
            int key = idx >> 4, c4 = (idx & 15) << 2;
            float4* pk = (float4*)&Ks[key * LDP + c4];
            float4 kv = *pk;
            kv.x = to_tf32(kv.x); kv.y = to_tf32(kv.y);
            kv.z = to_tf32(kv.z); kv.w = to_tf32(kv.w);
            *pk = kv;
            float4* pv = (float4*)&Vs[key * LDV + c4];
            float4 vv = *pv;
            vv.x = to_tf32(vv.x); vv.y = to_tf32(vv.y);
            vv.z = to_tf32(vv.z); vv.w = to_tf32(vv.w);
            *pv = vv;
        }
        __syncthreads();

        const int   dr0 = t0 + qr + gi - s0;
        const float ai0 = exp2f((float)dr0 * L2G);
        const float ai1 = exp2f((float)(dr0 + 8) * L2G);

        // ---- stage 1: S = Q K^T (k0-outer: independent accumulators) ----
        float s[8][4];
        #pragma unroll
        for (int nt = 0; nt < 8; nt++)
            #pragma unroll
            for (int u = 0; u < 4; u++) s[nt][u] = 0.f;

        #pragma unroll
        for (int k0 = 0; k0 < 8; k0++) {
            #pragma unroll
            for (int nt = 0; nt < 8; nt++) {
                int ba = (nt * 8 + gi) * LDP + k0 * 8 + ti4;
                unsigned b0 = __float_as_uint(Ks[ba]);
                unsigned b1 = __float_as_uint(Ks[ba + 4]);
                mma_tf32(s[nt][0], s[nt][1], s[nt][2], s[nt][3],
                         qa[k0][0], qa[k0][1], qa[k0][2], qa[k0][3], b0, b1);
            }
        }

        // ---- decay + causal mask, tf32, to S buffer ----
        #pragma unroll
        for (int nt = 0; nt < 8; nt++) {
            const int je = nt * 8 + 2 * ti4, jo = je + 1;
            const float be = binv[je], bo = binv[jo];
            float c0 = (dr0     >= je) ? s[nt][0] * ai0 * be : 0.f;
            float c1 = (dr0     >= jo) ? s[nt][1] * ai0 * bo : 0.f;
            float c2 = (dr0 + 8 >= je) ? s[nt][2] * ai1 * be : 0.f;
            float c3 = (dr0 + 8 >= jo) ? s[nt][3] * ai1 * bo : 0.f;
            *(float2*)&sw[gi * LDP + je]       = make_float2(to_tf32(c0), to_tf32(c1));
            *(float2*)&sw[(gi + 8) * LDP + je] = make_float2(to_tf32(c2), to_tf32(c3));
        }
        __syncwarp();

        // ---- A fragments of S ----
        unsigned sa[8][4];
        #pragma unroll
        for (int k0 = 0; k0 < 8; k0++) {
            int base = gi * LDP + k0 * 8 + ti4;
            sa[k0][0] = __float_as_uint(sw[base]);
            sa[k0][1] = __float_as_uint(sw[base + 8 * LDP]);
            sa[k0][2] = __float_as_uint(sw[base + 4]);
            sa[k0][3] = __float_as_uint(sw[base + 8 * LDP + 4]);
        }

        // ---- stage 2: O += S V (k0-outer: independent accumulators) ----
        #pragma unroll
        for (int k0 = 0; k0 < 8; k0++) {
            #pragma unroll
            for (int nt = 0; nt < 8; nt++) {
                int va = (k0 * 8 + ti4) * LDV + nt * 8 + gi;
                unsigned b0 = __float_as_uint(Vs[va]);
                unsigned b1 = __float_as_uint(Vs[va + 4 * LDV]);
                mma_tf32(o[nt][0], o[nt][1], o[nt][2], o[nt][3],
                         sa[k0][0], sa[k0][1], sa[k0][2], sa[k0][3], b0, b1);
            }
        }
        // no trailing bar: next iteration's post-wait __syncthreads orders
        // compute(it) before any overwrite of this buffer (it+2 prefetch).
    }

    // ================= fused GroupNorm epilogue + transposed store ===========
    const int t_lo = t0 + qr + gi;
    float* outb = out + (size_t)b * T_SEQ * 64;

    #pragma unroll
    for (int nt = 0; nt < 8; nt++) {
        float sl = o[nt][0] + o[nt][1];
        float ql = fmaf(o[nt][0], o[nt][0], o[nt][1] * o[nt][1]);
        float sh = o[nt][2] + o[nt][3];
        float qh = fmaf(o[nt][2], o[nt][2], o[nt][3] * o[nt][3]);
        sl += __shfl_xor_sync(0xffffffffu, sl, 1);
        ql += __shfl_xor_sync(0xffffffffu, ql, 1);
        sh += __shfl_xor_sync(0xffffffffu, sh, 1);
        qh += __shfl_xor_sync(0xffffffffu, qh, 1);
        sl += __shfl_xor_sync(0xffffffffu, sl, 2);
        ql += __shfl_xor_sync(0xffffffffu, ql, 2);
        sh += __shfl_xor_sync(0xffffffffu, sh, 2);
        qh += __shfl_xor_sync(0xffffffffu, qh, 2);

        float mul = sl * 0.125f, muh = sh * 0.125f;
        float rl = rsqrtf(fmaf(-mul, mul, ql * 0.125f) + 1e-6f);
        float rh = rsqrtf(fmaf(-muh, muh, qh * 0.125f) + 1e-6f);

        const int c0 = nt * 8 + 2 * ti4, c1 = c0 + 1;
        const float w0 = gw[c0], w1 = gw[c1];
        const float b0 = gb[c0], b1 = gb[c1];
        outb[(size_t)c0 * T_SEQ + t_lo]     = (o[nt][0] - mul) * rl * w0 + b0;
        outb[(size_t)c1 * T_SEQ + t_lo]     = (o[nt][1] - mul) * rl * w1 + b1;
        outb[(size_t)c0 * T_SEQ + t_lo + 8] = (o[nt][2] - muh) * rh * w0 + b0;
        outb[(size_t)c1 * T_SEQ + t_lo + 8] = (o[nt][3] - muh) * rh * w1 + b1;
    }
}

// =============================================================================
extern "C" void kernel_launch(void* const* d_in, const int* in_sizes, int n_in,
                              void* d_out, int out_size)
{
    (void)in_sizes; (void)n_in; (void)out_size;
    const float* X  = (const float*)d_in[0];
    const float* WQ = (const float*)d_in[1];
    const float* WK = (const float*)d_in[2];
    const float* WV = (const float*)d_in[3];
    const float* gw = (const float*)d_in[4];
    const float* gb = (const float*)d_in[5];
    float* out = (float*)d_out;

    cudaFuncSetAttribute(proj_kernel, cudaFuncAttributeMaxDynamicSharedMemorySize, PROJ_SMEM);
    cudaFuncSetAttribute(attn_kernel, cudaFuncAttributeMaxDynamicSharedMemorySize, ATTN_SMEM);

    proj_kernel<<<NROWS / 64, 256, PROJ_SMEM>>>(X, WQ, WK, WV);
    attn_kernel<<<NROWS / 64, 128, ATTN_SMEM>>>(gw, gb, out);
}

// round 15
// speedup vs baseline: 1.1889x; 1.0667x over previous
#include <cuda_runtime.h>
#include <math.h>

#define T_SEQ   8192
#define NBATCH  2
#define NROWS   (NBATCH * T_SEQ)   // 16384
#define WIN     448                // gamma^448/(1-gamma) ~ 2e-5: safe at 1e-3
#define L2G     (-0.04580369f)     // log2(0.96875)

// ---------------- scratch (device globals; no allocs allowed) ----------------
__device__ float g_Q[NROWS * 64];
__device__ float g_K[NROWS * 64];
__device__ float g_V[NROWS * 64];

__device__ __forceinline__ float to_tf32(float x) {
    unsigned u; asm("cvt.rna.tf32.f32 %0, %1;" : "=r"(u) : "f"(x));
    return __uint_as_float(u);
}

// m16n8k8 tf32 warp MMA (family-agnostic PTX, compiles for compute_103)
__device__ __forceinline__ void mma_tf32(float& d0, float& d1, float& d2, float& d3,
                                         unsigned a0, unsigned a1, unsigned a2, unsigned a3,
                                         unsigned b0, unsigned b1) {
    asm volatile("mma.sync.aligned.m16n8k8.row.col.f32.tf32.tf32.f32 "
                 "{%0,%1,%2,%3}, {%4,%5,%6,%7}, {%8,%9}, {%0,%1,%2,%3};"
                 : "+f"(d0), "+f"(d1), "+f"(d2), "+f"(d3)
                 : "r"(a0), "r"(a1), "r"(a2), "r"(a3), "r"(b0), "r"(b1));
}

// =================== Kernel 1: QKV proj (3xTF32 tensor-core) =================
#define LDXP 68    // X smem pad: frag banks gi*4+ti4 -> conflict-free
#define LDW  200   // W smem pad: 200 mod 32 = 8 -> frag banks ti4*8+gi -> CF
#define PROJ_SMEM ((64 * LDXP + 64 * LDW) * 4)   // 68608 B

__global__ __launch_bounds__(256, 2) void proj_kernel(
    const float* __restrict__ X,
    const float* __restrict__ WQ,
    const float* __restrict__ WK,
    const float* __restrict__ WV)
{
    extern __shared__ float sm[];
    float* Xs = sm;                // [64][LDXP]
    float* Ws = sm + 64 * LDXP;    // [64 k][LDW], cols 0..191 = WQ|WK|WV

    const int tid  = threadIdx.x;
    const int lane = tid & 31;
    const int w    = tid >> 5;
    const int gi   = lane >> 2;
    const int ti4  = lane & 3;
    const int wr   = w & 3;        // row group
    const int wh   = w >> 2;       // column half
    const int r0   = blockIdx.x * 64;

    for (int idx = tid; idx < 64 * 16; idx += 256) {
        int row = idx >> 4, c4 = (idx & 15) << 2;
        *(float4*)&Xs[row * LDXP + c4] = *(const float4*)&X[(r0 + row) * 64 + c4];
    }
    {
        const float* Wsrc[3] = {WQ, WK, WV};
        #pragma unroll
        for (int m = 0; m < 3; m++)
            for (int idx = tid; idx < 64 * 16; idx += 256) {
                int row = idx >> 4, c4 = (idx & 15) << 2;
                *(float4*)&Ws[row * LDW + m * 64 + c4] =
                    *(const float4*)&Wsrc[m][row * 64 + c4];
            }
    }
    __syncthreads();

    const int qrow = wr * 16 + gi;
    unsigned ahi[8][4], alo[8][4];
    #pragma unroll
    for (int k0 = 0; k0 < 8; k0++) {
        float xv[4];
        xv[0] = Xs[qrow * LDXP + k0 * 8 + ti4];
        xv[1] = Xs[(qrow + 8) * LDXP + k0 * 8 + ti4];
        xv[2] = Xs[qrow * LDXP + k0 * 8 + ti4 + 4];
        xv[3] = Xs[(qrow + 8) * LDXP + k0 * 8 + ti4 + 4];
        #pragma unroll
        for (int u = 0; u < 4; u++) {
            float hi = to_tf32(xv[u]);
            ahi[k0][u] = __float_as_uint(hi);
            alo[k0][u] = __float_as_uint(to_tf32(xv[u] - hi));
        }
    }

    float* outp[3] = {g_Q, g_K, g_V};
    for (int m = 0; m < 3; m++) {
        float accA[4][4], accB[4][4];
        #pragma unroll
        for (int nt = 0; nt < 4; nt++)
            #pragma unroll
            for (int u = 0; u < 4; u++) { accA[nt][u] = 0.f; accB[nt][u] = 0.f; }

        #pragma unroll
        for (int k0 = 0; k0 < 8; k0++) {
            #pragma unroll
            for (int ntl = 0; ntl < 4; ntl++) {
                const int ncol = m * 64 + (wh * 4 + ntl) * 8 + gi;
                float b0f = Ws[(k0 * 8 + ti4) * LDW + ncol];
                float b1f = Ws[(k0 * 8 + ti4 + 4) * LDW + ncol];
                float b0h = to_tf32(b0f), b1h = to_tf32(b1f);
                unsigned ub0h = __float_as_uint(b0h);
                unsigned ub1h = __float_as_uint(b1h);
                unsigned ub0l = __float_as_uint(to_tf32(b0f - b0h));
                unsigned ub1l = __float_as_uint(to_tf32(b1f - b1h));
                mma_tf32(accA[ntl][0], accA[ntl][1], accA[ntl][2], accA[ntl][3],
                         ahi[k0][0], ahi[k0][1], ahi[k0][2], ahi[k0][3], ub0h, ub1h);
                mma_tf32(accB[ntl][0], accB[ntl][1], accB[ntl][2], accB[ntl][3],
                         ahi[k0][0], ahi[k0][1], ahi[k0][2], ahi[k0][3], ub0l, ub1l);
                mma_tf32(accB[ntl][0], accB[ntl][1], accB[ntl][2], accB[ntl][3],
                         alo[k0][0], alo[k0][1], alo[k0][2], alo[k0][3], ub0h, ub1h);
            }
        }
        float* op = outp[m];
        #pragma unroll
        for (int ntl = 0; ntl < 4; ntl++) {
            int col = (wh * 4 + ntl) * 8 + 2 * ti4;
            *(float2*)&op[(r0 + qrow) * 64 + col] =
                make_float2(accA[ntl][0] + accB[ntl][0], accA[ntl][1] + accB[ntl][1]);
            *(float2*)&op[(r0 + qrow + 8) * 64 + col] =
                make_float2(accA[ntl][2] + accB[ntl][2], accA[ntl][3] + accB[ntl][3]);
        }
    }
}

// ========= Kernel 2: warp-MMA tf32 attention + fused GN (low-reg) ===========
// CTA = 64 q-rows, 4 warps x 16 rows, 128 threads, grid 256. Key tiles of 64.
// A-fragments (Q, S) loaded per-k0 from smem (4 conflict-free LDS.32 feeding
// 8 MMAs) instead of preloaded 32-reg arrays -> regs <=168 -> 3 CTAs/SM,
// single wave. Dedicated S region (Q persists for per-tile frag reloads).
#define LDP 68   // pad for Q/K/S
#define LDV 72   // pad for V

#define SM_BINV 0
#define SM_QS   64                       // [64][LDP] persistent Q
#define SM_SS   (SM_QS + 64 * LDP)       // [64][LDP] S buffer
#define SM_KS   (SM_SS + 64 * LDP)       // [64][LDP]
#define SM_VS   (SM_KS + 64 * LDP)       // [64][LDV]
#define ATTN_SMEM ((SM_VS + 64 * LDV) * 4)   // 70912 B -> 3 CTAs/SM

__global__ __launch_bounds__(128, 3) void attn_kernel(
    const float* __restrict__ gw, const float* __restrict__ gb,
    float* __restrict__ out)
{
    extern __shared__ float sm[];
    float* binv = sm + SM_BINV;
    float* Qs   = sm + SM_QS;
    float* Ks   = sm + SM_KS;
    float* Vs   = sm + SM_VS;

    const int tid  = threadIdx.x;
    const int lane = tid & 31;
    const int w    = tid >> 5;
    const int gi   = lane >> 2;   // 0..7
    const int ti4  = lane & 3;    // 0..3

    const int r0 = blockIdx.x * 64;
    const int b  = r0 >> 13;
    const int t0 = r0 & (T_SEQ - 1);
    const int bT = b << 13;

    if (tid < 64) binv[tid] = exp2f(-(float)tid * L2G);   // gamma^-j

    // ---- stage Q (tf32), persistent across tiles ----
    for (int idx = tid; idx < 64 * 16; idx += 128) {
        int row = idx >> 4, c4 = (idx & 15) << 2;
        float4 v = *(const float4*)&g_Q[(r0 + row) * 64 + c4];
        v.x = to_tf32(v.x); v.y = to_tf32(v.y); v.z = to_tf32(v.z); v.w = to_tf32(v.w);
        *(float4*)&Qs[row * LDP + c4] = v;
    }
    __syncthreads();

    const int qr = w * 16;
    float* sw = sm + SM_SS + qr * LDP;   // warp-private S rows
    const float* qf = &Qs[(qr + gi) * LDP + ti4];   // A-frag base (Q)
    const float* sf = sw + gi * LDP + ti4;          // A-frag base (S)

    float o[8][4];
    #pragma unroll
    for (int nt = 0; nt < 8; nt++)
        #pragma unroll
        for (int u = 0; u < 4; u++) o[nt][u] = 0.f;

    int ks = t0 - WIN; if (ks < 0) ks = 0;

    for (int s0 = ks; s0 < t0 + 64; s0 += 64) {
        // ---- stage K, V tiles (tf32) ----
        for (int idx = tid; idx < 64 * 16; idx += 128) {
            int key = idx >> 4, c4 = (idx & 15) << 2;
            float4 kv = *(const float4*)&g_K[(bT + s0 + key) * 64 + c4];
            kv.x = to_tf32(kv.x); kv.y = to_tf32(kv.y);
            kv.z = to_tf32(kv.z); kv.w = to_tf32(kv.w);
            *(float4*)&Ks[key * LDP + c4] = kv;
            float4 vv = *(const float4*)&g_V[(bT + s0 + key) * 64 + c4];
            vv.x = to_tf32(vv.x); vv.y = to_tf32(vv.y);
            vv.z = to_tf32(vv.z); vv.w = to_tf32(vv.w);
            *(float4*)&Vs[key * LDV + c4] = vv;
        }
        __syncthreads();

        const int   dr0 = t0 + qr + gi - s0;
        const float ai0 = exp2f((float)dr0 * L2G);
        const float ai1 = exp2f((float)(dr0 + 8) * L2G);

        // ---- stage 1: S = Q K^T (k0-outer; Q-frag loaded per k0) ----
        float s[8][4];
        #pragma unroll
        for (int nt = 0; nt < 8; nt++)
            #pragma unroll
            for (int u = 0; u < 4; u++) s[nt][u] = 0.f;

        #pragma unroll
        for (int k0 = 0; k0 < 8; k0++) {
            unsigned a0 = __float_as_uint(qf[k0 * 8]);
            unsigned a1 = __float_as_uint(qf[k0 * 8 + 8 * LDP]);
            unsigned a2 = __float_as_uint(qf[k0 * 8 + 4]);
            unsigned a3 = __float_as_uint(qf[k0 * 8 + 8 * LDP + 4]);
            #pragma unroll
            for (int nt = 0; nt < 8; nt++) {
                int ba = (nt * 8 + gi) * LDP + k0 * 8 + ti4;
                unsigned b0 = __float_as_uint(Ks[ba]);
                unsigned b1 = __float_as_uint(Ks[ba + 4]);
                mma_tf32(s[nt][0], s[nt][1], s[nt][2], s[nt][3],
                         a0, a1, a2, a3, b0, b1);
            }
        }

        // ---- decay + causal mask, tf32, to S buffer ----
        #pragma unroll
        for (int nt = 0; nt < 8; nt++) {
            const int je = nt * 8 + 2 * ti4, jo = je + 1;
            const float be = binv[je], bo = binv[jo];
            float c0 = (dr0     >= je) ? s[nt][0] * ai0 * be : 0.f;
            float c1 = (dr0     >= jo) ? s[nt][1] * ai0 * bo : 0.f;
            float c2 = (dr0 + 8 >= je) ? s[nt][2] * ai1 * be : 0.f;
            float c3 = (dr0 + 8 >= jo) ? s[nt][3] * ai1 * bo : 0.f;
            *(float2*)&sw[gi * LDP + je]       = make_float2(to_tf32(c0), to_tf32(c1));
            *(float2*)&sw[(gi + 8) * LDP + je] = make_float2(to_tf32(c2), to_tf32(c3));
        }
        __syncwarp();

        // ---- stage 2: O += S V (k0-outer; S-frag loaded per k0) ----
        #pragma unroll
        for (int k0 = 0; k0 < 8; k0++) {
            unsigned a0 = __float_as_uint(sf[k0 * 8]);
            unsigned a1 = __float_as_uint(sf[k0 * 8 + 8 * LDP]);
            unsigned a2 = __float_as_uint(sf[k0 * 8 + 4]);
            unsigned a3 = __float_as_uint(sf[k0 * 8 + 8 * LDP + 4]);
            #pragma unroll
            for (int nt = 0; nt < 8; nt++) {
                int va = (k0 * 8 + ti4) * LDV + nt * 8 + gi;
                unsigned b0 = __float_as_uint(Vs[va]);
                unsigned b1 = __float_as_uint(Vs[va + 4 * LDV]);
                mma_tf32(o[nt][0], o[nt][1], o[nt][2], o[nt][3],
                         a0, a1, a2, a3, b0, b1);
            }
        }
        __syncthreads();   // compute done before next tile's K/V overwrite
    }

    // ================= fused GroupNorm epilogue + transposed store ===========
    const int t_lo = t0 + qr + gi;
    float* outb = out + (size_t)b * T_SEQ * 64;

    #pragma unroll
    for (int nt = 0; nt < 8; nt++) {
        float sl = o[nt][0] + o[nt][1];
        float ql = fmaf(o[nt][0], o[nt][0], o[nt][1] * o[nt][1]);
        float sh = o[nt][2] + o[nt][3];
        float qh = fmaf(o[nt][2], o[nt][2], o[nt][3] * o[nt][3]);
        sl += __shfl_xor_sync(0xffffffffu, sl, 1);
        ql += __shfl_xor_sync(0xffffffffu, ql, 1);
        sh += __shfl_xor_sync(0xffffffffu, sh, 1);
        qh += __shfl_xor_sync(0xffffffffu, qh, 1);
        sl += __shfl_xor_sync(0xffffffffu, sl, 2);
        ql += __shfl_xor_sync(0xffffffffu, ql, 2);
        sh += __shfl_xor_sync(0xffffffffu, sh, 2);
        qh += __shfl_xor_sync(0xffffffffu, qh, 2);

        float mul = sl * 0.125f, muh = sh * 0.125f;
        float rl = rsqrtf(fmaf(-mul, mul, ql * 0.125f) + 1e-6f);
        float rh = rsqrtf(fmaf(-muh, muh, qh * 0.125f) + 1e-6f);

        const int c0 = nt * 8 + 2 * ti4, c1 = c0 + 1;
        const float w0 = gw[c0], w1 = gw[c1];
        const float b0 = gb[c0], b1 = gb[c1];
        outb[(size_t)c0 * T_SEQ + t_lo]     = (o[nt][0] - mul) * rl * w0 + b0;
        outb[(size_t)c1 * T_SEQ + t_lo]     = (o[nt][1] - mul) * rl * w1 + b1;
        outb[(size_t)c0 * T_SEQ + t_lo + 8] = (o[nt][2] - muh) * rh * w0 + b0;
        outb[(size_t)c1 * T_SEQ + t_lo + 8] = (o[nt][3] - muh) * rh * w1 + b1;
    }
}

// =============================================================================
extern "C" void kernel_launch(void* const* d_in, const int* in_sizes, int n_in,
                              void* d_out, int out_size)
{
    (void)in_sizes; (void)n_in; (void)out_size;
    const float* X  = (const float*)d_in[0];
    const float* WQ = (const float*)d_in[1];
    const float* WK = (const float*)d_in[2];
    const float* WV = (const float*)d_in[3];
    const float* gw = (const float*)d_in[4];
    const float* gb = (const float*)d_in[5];
    float* out = (float*)d_out;

    cudaFuncSetAttribute(proj_kernel, cudaFuncAttributeMaxDynamicSharedMemorySize, PROJ_SMEM);
    cudaFuncSetAttribute(attn_kernel, cudaFuncAttributeMaxDynamicSharedMemorySize, ATTN_SMEM);

    proj_kernel<<<NROWS / 64, 256, PROJ_SMEM>>>(X, WQ, WK, WV);
    attn_kernel<<<NROWS / 64, 128, ATTN_SMEM>>>(gw, gb, out);
}